// round 12
// baseline (speedup 1.0000x reference)
#include <cuda_runtime.h>

typedef unsigned long long u64;
typedef unsigned int u32;

#define TPB   128
#define EPW   4                     // elements per warp
#define EPB   16                    // elements per block
#define VSTR  10                    // LUT stride: bank-pair = 5v+jj, 5 odd -> same-jj conflict-free
#define LUTW  (8 * 16 * VSTR)       // 1280 words (5 KB)

// ---- packed fp32x2 helpers (sm_103a dual-fp32: 2x FFMA throughput) ----
__device__ __forceinline__ u64 pk(float lo, float hi) {
    u64 r; asm("mov.b64 %0, {%1, %2};" : "=l"(r) : "f"(lo), "f"(hi)); return r;
}
__device__ __forceinline__ void upk(float& lo, float& hi, u64 v) {
    asm("mov.b64 {%0, %1}, %2;" : "=f"(lo), "=f"(hi) : "l"(v));
}
__device__ __forceinline__ u64 fma2(u64 a, u64 b, u64 c) {
    u64 d; asm("fma.rn.f32x2 %0, %1, %2, %3;" : "=l"(d) : "l"(a), "l"(b), "l"(c)); return d;
}
__device__ __forceinline__ u64 add2(u64 a, u64 b) {
    u64 d; asm("add.rn.f32x2 %0, %1, %2;" : "=l"(d) : "l"(a), "l"(b)); return d;
}

__global__ void __launch_bounds__(TPB, 3) snn_kernel(
    const float* __restrict__ x,  const float* __restrict__ W1,
    const float* __restrict__ b1, const float* __restrict__ W2,
    const float* __restrict__ b2, float* __restrict__ out, int B)
{
    __shared__ __align__(16) float tab[LUTW];   // nibble LUT only; x stays in gmem/L1D

    const int tid = threadIdx.x;
    const int lid = tid & 31;
    const int wid = tid >> 5;
    const int q   = lid >> 3;       // elem within warp (0..3)
    const int r   = lid & 7;        // unit-slice (0..7)
    const int gbase = blockIdx.x * EPB;
    const int eg    = gbase + wid * EPW + q;

    // ======== nibble LUT (b2 pre-added to p=0: bit-exact bias-first) ========
    for (int idx = tid; idx < LUTW; idx += TPB) {
        int j = idx % 10;
        int v = (idx / 10) & 15;
        int p = idx / 160;
        float s = (p == 0) ? b2[j] : 0.0f;
#pragma unroll
        for (int bb = 0; bb < 4; ++bb)
            if ((v >> bb) & 1) s += W2[j * 32 + 4 * p + bb];
        tab[idx] = s;
    }

    // ======== per-lane register weights: unit-pairs (r, r+16) and (r+8, r+24) ======
    u64 wA[28], wB[28];
    {
        const float4* p0 = reinterpret_cast<const float4*>(W1 + r * 28);
        const float4* p1 = reinterpret_cast<const float4*>(W1 + (r + 16) * 28);
        const float4* p2 = reinterpret_cast<const float4*>(W1 + (r + 8) * 28);
        const float4* p3 = reinterpret_cast<const float4*>(W1 + (r + 24) * 28);
#pragma unroll
        for (int c = 0; c < 7; ++c) {
            float4 a = __ldg(p0 + c), b = __ldg(p1 + c);
            float4 e = __ldg(p2 + c), f = __ldg(p3 + c);
            wA[4 * c + 0] = pk(a.x, b.x); wA[4 * c + 1] = pk(a.y, b.y);
            wA[4 * c + 2] = pk(a.z, b.z); wA[4 * c + 3] = pk(a.w, b.w);
            wB[4 * c + 0] = pk(e.x, f.x); wB[4 * c + 1] = pk(e.y, f.y);
            wB[4 * c + 2] = pk(e.z, f.z); wB[4 * c + 3] = pk(e.w, f.w);
        }
    }
    const u64 hb0 = pk(__ldg(&b1[r]),     __ldg(&b1[r + 16]));
    const u64 hb1 = pk(__ldg(&b1[r + 8]), __ldg(&b1[r + 24]));

    // layer-2 lane roles: lanes 0..19 -> (elem me, output-pair jj); 20..31 mirror
    const int jj = lid % 5;
    const int me = (lid / 5) & 3;
    const float* tj = tab + 2 * jj;
    const u32 sel = (u32)me | (((u32)me + 4) << 4);   // byte_perm: byte 'me' of a,b

    __syncthreads();

    // per-lane x base (8-lane broadcast per elem; LDG sector-packs -> ~1 wf/quad-load)
    const int esafe = (eg < B) ? eg : (B - 1);
    const float4* xq4 = reinterpret_cast<const float4*>(x + (size_t)esafe * 784);

    u64 v1a = 0ull, v1b = 0ull, v2p = 0ull, accp = 0ull;

    // ================= main recurrence: 7 t-quads ==========================
#pragma unroll 1
    for (int tq = 0; tq < 7; ++tq) {
        // ---- layer 1 for t = 4tq..4tq+3 concurrently (4 independent exact chains) ----
        u64 A0[4] = { hb0, hb0, hb0, hb0 };   // pair (r, r+16)  per t-slot
        u64 A1[4] = { hb1, hb1, hb1, hb1 };   // pair (r+8,r+24) per t-slot
        const float4* xp = xq4 + tq;          // x[e][i][4tq..4tq+3], stride 7 float4 per i
#pragma unroll
        for (int i = 0; i < 28; ++i) {
            float4 xv = __ldg(xp + i * 7);
            u64 d0 = pk(xv.x, xv.x);
            A0[0] = fma2(d0, wA[i], A0[0]); A1[0] = fma2(d0, wB[i], A1[0]);
            u64 d1 = pk(xv.y, xv.y);
            A0[1] = fma2(d1, wA[i], A0[1]); A1[1] = fma2(d1, wB[i], A1[1]);
            u64 d2 = pk(xv.z, xv.z);
            A0[2] = fma2(d2, wA[i], A0[2]); A1[2] = fma2(d2, wB[i], A1[2]);
            u64 d3 = pk(xv.w, xv.w);
            A0[3] = fma2(d3, wA[i], A0[3]); A1[3] = fma2(d3, wB[i], A1[3]);
        }

        // ---- serial IF / ballot / LUT tail for the 4 timesteps ----
#pragma unroll
        for (int s4 = 0; s4 < 4; ++s4) {
            v1a = add2(v1a, A0[s4]);
            v1b = add2(v1b, A1[s4]);
            float fa0, fa1, fb0, fb1;
            upk(fa0, fa1, v1a);
            upk(fb0, fb1, v1b);
            bool sr0  = (fa0 >= 1.0f);      // unit r
            bool sr16 = (fa1 >= 1.0f);      // unit r+16
            bool sr8  = (fb0 >= 1.0f);      // unit r+8
            bool sr24 = (fb1 >= 1.0f);      // unit r+24
            u32 B0 = __ballot_sync(0xffffffffu, sr0);
            u32 B1 = __ballot_sync(0xffffffffu, sr8);
            u32 B2 = __ballot_sync(0xffffffffu, sr16);
            u32 B3 = __ballot_sync(0xffffffffu, sr24);
            v1a = pk(sr0 ? 0.0f : fa0, sr16 ? 0.0f : fa1);
            v1b = pk(sr8 ? 0.0f : fb0, sr24 ? 0.0f : fb1);

            // 32-bit spike mask of elem 'me' via 3 PRMTs (bit k = unit k)
            u32 lo16 = __byte_perm(B0, B1, sel);
            u32 hi16 = __byte_perm(B2, B3, sel);
            u32 M    = __byte_perm(lo16, hi16, 0x5410);

            // layer 2: 8 nibble-LUT lookups (bias folded in p=0; ascending-p order)
            u64 h2 = *reinterpret_cast<const u64*>(tj + (M & 15u) * VSTR);
            h2 = add2(h2, *reinterpret_cast<const u64*>(tj + ((M >> 4)  & 15u) * VSTR + 160));
            h2 = add2(h2, *reinterpret_cast<const u64*>(tj + ((M >> 8)  & 15u) * VSTR + 320));
            h2 = add2(h2, *reinterpret_cast<const u64*>(tj + ((M >> 12) & 15u) * VSTR + 480));
            h2 = add2(h2, *reinterpret_cast<const u64*>(tj + ((M >> 16) & 15u) * VSTR + 640));
            h2 = add2(h2, *reinterpret_cast<const u64*>(tj + ((M >> 20) & 15u) * VSTR + 800));
            h2 = add2(h2, *reinterpret_cast<const u64*>(tj + ((M >> 24) & 15u) * VSTR + 960));
            h2 = add2(h2, *reinterpret_cast<const u64*>(tj + ((M >> 28) & 15u) * VSTR + 1120));

            // IF layer 2 + rate accumulation
            v2p = add2(v2p, h2);
            float g0, g1; upk(g0, g1, v2p);
            bool t0 = (g0 >= 1.0f), t1 = (g1 >= 1.0f);
            accp = add2(accp, pk(t0 ? 1.0f : 0.0f, t1 ? 1.0f : 0.0f));
            v2p = pk(t0 ? 0.0f : g0, t1 ? 0.0f : g1);
        }
    }

    // ---- output: lanes 0..19 write their (elem, j-pair) firing rates ----
    int ge = gbase + wid * EPW + me;
    if (lid < 20 && ge < B) {
        float a0, a1; upk(a0, a1, accp);
        *reinterpret_cast<float2*>(out + (size_t)ge * 10 + 2 * jj) =
            make_float2(a0 * (1.0f / 28.0f), a1 * (1.0f / 28.0f));
    }
}

extern "C" void kernel_launch(void* const* d_in, const int* in_sizes, int n_in,
                              void* d_out, int out_size) {
    const float* x  = (const float*)d_in[0];
    const float* W1 = (const float*)d_in[1];
    const float* b1 = (const float*)d_in[2];
    const float* W2 = (const float*)d_in[3];
    const float* b2 = (const float*)d_in[4];
    float* out = (float*)d_out;

    int B = in_sizes[0] / 784;
    int grid = (B + EPB - 1) / EPB;
    snn_kernel<<<grid, TPB>>>(x, W1, b1, W2, b2, out, B);
}

// round 13
// speedup vs baseline: 1.4694x; 1.4694x over previous
#include <cuda_runtime.h>

typedef unsigned long long u64;
typedef unsigned int u32;

#define TPB   128
#define EPW   4                     // elements per warp
#define EPB   16                    // elements per block
#define TROW  32                    // words per t-row
#define IMG   904                   // 28*32 + 8 skew; 904%32=8 -> elem quads disjoint
#define XW    (EPB * IMG)           // 14464 words
#define SMEMW (XW + 16)             // 57920 B -> 3 blocks/SM

// byte-LUT in gmem (L1D-cached): [p4][byte][j], j stride 10
__device__ float g_lut[4 * 256 * 10];

// ---- packed fp32x2 helpers (sm_103a dual-fp32: 2x FFMA throughput) ----
__device__ __forceinline__ u64 pk(float lo, float hi) {
    u64 r; asm("mov.b64 %0, {%1, %2};" : "=l"(r) : "f"(lo), "f"(hi)); return r;
}
__device__ __forceinline__ void upk(float& lo, float& hi, u64 v) {
    asm("mov.b64 {%0, %1}, %2;" : "=f"(lo), "=f"(hi) : "l"(v));
}
__device__ __forceinline__ u64 fma2(u64 a, u64 b, u64 c) {
    u64 d; asm("fma.rn.f32x2 %0, %1, %2, %3;" : "=l"(d) : "l"(a), "l"(b), "l"(c)); return d;
}
__device__ __forceinline__ u64 add2(u64 a, u64 b) {
    u64 d; asm("add.rn.f32x2 %0, %1, %2;" : "=l"(d) : "l"(a), "l"(b)); return d;
}

// layer-1 FMA2 chain for timestep (tt): exact serial i-order, units packed (u,u+16)
#define COMPUTE_H(tt, H0, H1)                                                   \
    do {                                                                        \
        const float4* xr_ = reinterpret_cast<const float4*>(xbase + (tt) * TROW); \
        (H0) = hb0; (H1) = hb1;                                                 \
        _Pragma("unroll")                                                       \
        for (int k = 0; k < 7; ++k) {                                           \
            float4 xv = xr_[k];                                                 \
            u64 d0 = pk(xv.x, xv.x);                                            \
            (H0) = fma2(d0, wA[4 * k + 0], (H0));                               \
            (H1) = fma2(d0, wB[4 * k + 0], (H1));                               \
            u64 d1 = pk(xv.y, xv.y);                                            \
            (H0) = fma2(d1, wA[4 * k + 1], (H0));                               \
            (H1) = fma2(d1, wB[4 * k + 1], (H1));                               \
            u64 d2 = pk(xv.z, xv.z);                                            \
            (H0) = fma2(d2, wA[4 * k + 2], (H0));                               \
            (H1) = fma2(d2, wB[4 * k + 2], (H1));                               \
            u64 d3 = pk(xv.w, xv.w);                                            \
            (H0) = fma2(d3, wA[4 * k + 3], (H0));                               \
            (H1) = fma2(d3, wB[4 * k + 3], (H1));                               \
        }                                                                       \
    } while (0)

// ======== prologue kernel: build byte-LUT (R4's exact fp order) ========
__global__ void build_lut(const float* __restrict__ W2)
{
    int idx = blockIdx.x * blockDim.x + threadIdx.x;
    if (idx < 4 * 256 * 10) {
        int j  = idx % 10;
        int vv = (idx / 10) & 255;
        int p4 = idx / 2560;
        float slo = 0.0f, shi = 0.0f;
#pragma unroll
        for (int bb = 0; bb < 4; ++bb)
            if ((vv >> bb) & 1) slo += W2[j * 32 + 8 * p4 + bb];
#pragma unroll
        for (int bb = 0; bb < 4; ++bb)
            if ((vv >> (4 + bb)) & 1) shi += W2[j * 32 + 8 * p4 + 4 + bb];
        g_lut[idx] = slo + shi;
    }
}

extern __shared__ __align__(16) float smem_f[];

__global__ void __launch_bounds__(TPB, 3) snn_kernel(
    const float* __restrict__ x,  const float* __restrict__ W1,
    const float* __restrict__ b1, const float* __restrict__ W2,
    const float* __restrict__ b2, float* __restrict__ out, int B)
{
    float* smx = smem_f;            // staged x, t-major rows

    const int tid = threadIdx.x;
    const int lid = tid & 31;
    const int wid = tid >> 5;
    const int q   = lid >> 3;       // elem within warp (0..3)
    const int r   = lid & 7;        // unit-slice (0..7)
    const int eLocal = wid * EPW + q;
    const int gbase  = blockIdx.x * EPB;

    // ======== stage x: [e][t][i] rows (float4 LDG, scalar STS) ========
    for (int task = tid; task < EPB * 28; task += TPB) {
        int e = task / 28, i = task - e * 28;
        if (gbase + e < B) {
            const float4* src = reinterpret_cast<const float4*>(
                x + (size_t)(gbase + e) * 784 + i * 28);
            float* dst = smx + e * IMG + i;
#pragma unroll
            for (int c = 0; c < 7; ++c) {
                float4 v4 = __ldg(src + c);
                dst[(4 * c + 0) * TROW] = v4.x;
                dst[(4 * c + 1) * TROW] = v4.y;
                dst[(4 * c + 2) * TROW] = v4.z;
                dst[(4 * c + 3) * TROW] = v4.w;
            }
        }
    }

    // ======== per-lane register weights: unit-pairs (r, r+16) and (r+8, r+24) ======
    u64 wA[28], wB[28];
    {
        const float4* p0 = reinterpret_cast<const float4*>(W1 + r * 28);
        const float4* p1 = reinterpret_cast<const float4*>(W1 + (r + 16) * 28);
        const float4* p2 = reinterpret_cast<const float4*>(W1 + (r + 8) * 28);
        const float4* p3 = reinterpret_cast<const float4*>(W1 + (r + 24) * 28);
#pragma unroll
        for (int c = 0; c < 7; ++c) {
            float4 a = __ldg(p0 + c), b = __ldg(p1 + c);
            float4 e = __ldg(p2 + c), f = __ldg(p3 + c);
            wA[4 * c + 0] = pk(a.x, b.x); wA[4 * c + 1] = pk(a.y, b.y);
            wA[4 * c + 2] = pk(a.z, b.z); wA[4 * c + 3] = pk(a.w, b.w);
            wB[4 * c + 0] = pk(e.x, f.x); wB[4 * c + 1] = pk(e.y, f.y);
            wB[4 * c + 2] = pk(e.z, f.z); wB[4 * c + 3] = pk(e.w, f.w);
        }
    }
    const u64 hb0 = pk(__ldg(&b1[r]),     __ldg(&b1[r + 16]));
    const u64 hb1 = pk(__ldg(&b1[r + 8]), __ldg(&b1[r + 24]));

    // layer-2 lane roles: lanes 0..19 -> (elem me, output-pair jj); 20..31 mirror
    const int jj = lid % 5;
    const int me = (lid / 5) & 3;
    const u64 b2p = pk(__ldg(&b2[2 * jj]), __ldg(&b2[2 * jj + 1]));
    const float* lj = g_lut + 2 * jj;
    const u32 sel = (u32)me | (((u32)me + 4) << 4);   // byte_perm: byte 'me' of a,b

    __syncthreads();

    // ================= software-pipelined main recurrence (rolled) ================
    const float* xbase = smx + eLocal * IMG;

    u64 v1a = 0ull, v1b = 0ull, v2p = 0ull, accp = 0ull;
    u64 hc0, hc1;
    COMPUTE_H(0, hc0, hc1);          // prologue: h for t=0

#pragma unroll 2
    for (int t = 0; t < 28; ++t) {
        // ---- IF layer 1 on current h + spike ballots ----
        v1a = add2(v1a, hc0);
        v1b = add2(v1b, hc1);
        float fa0, fa1, fb0, fb1;
        upk(fa0, fa1, v1a);
        upk(fb0, fb1, v1b);
        bool sr0  = (fa0 >= 1.0f);      // unit r
        bool sr16 = (fa1 >= 1.0f);      // unit r+16
        bool sr8  = (fb0 >= 1.0f);      // unit r+8
        bool sr24 = (fb1 >= 1.0f);      // unit r+24
        u32 B0 = __ballot_sync(0xffffffffu, sr0);
        u32 B1 = __ballot_sync(0xffffffffu, sr8);
        u32 B2 = __ballot_sync(0xffffffffu, sr16);
        u32 B3 = __ballot_sync(0xffffffffu, sr24);
        v1a = pk(sr0 ? 0.0f : fa0, sr16 ? 0.0f : fa1);
        v1b = pk(sr8 ? 0.0f : fb0, sr24 ? 0.0f : fb1);

        // ---- 32-bit spike mask of elem 'me' via 3 PRMTs (bit k = unit k) ----
        u32 lo16 = __byte_perm(B0, B1, sel);
        u32 hi16 = __byte_perm(B2, B3, sel);
        u32 M    = __byte_perm(lo16, hi16, 0x5410);

        // ---- issue 4 byte-LUT LDGs now (L1D-resident table, 8B each) ----
        u64 l0 = __ldg(reinterpret_cast<const u64*>(lj + (M & 255u) * 10));
        u64 l1 = __ldg(reinterpret_cast<const u64*>(lj + ((M >> 8)  & 255u) * 10 + 2560));
        u64 l2 = __ldg(reinterpret_cast<const u64*>(lj + ((M >> 16) & 255u) * 10 + 5120));
        u64 l3 = __ldg(reinterpret_cast<const u64*>(lj + (M >> 24) * 10 + 7680));

        // ---- overlap: h for t+1 (t=27 prefetch discarded; in-bounds smem) ----
        u64 hn0, hn1;
        COMPUTE_H(t + 1, hn0, hn1);

        // ---- layer 2: consume LUT (b2-first, ascending p4: exact R4 order) ----
        u64 h2 = b2p;
        h2 = add2(h2, l0); h2 = add2(h2, l1); h2 = add2(h2, l2); h2 = add2(h2, l3);

        // ---- IF layer 2 + rate accumulation ----
        v2p = add2(v2p, h2);
        float g0, g1; upk(g0, g1, v2p);
        bool t0 = (g0 >= 1.0f), t1 = (g1 >= 1.0f);
        accp = add2(accp, pk(t0 ? 1.0f : 0.0f, t1 ? 1.0f : 0.0f));
        v2p = pk(t0 ? 0.0f : g0, t1 ? 0.0f : g1);

        hc0 = hn0; hc1 = hn1;
    }

    // ---- output: lanes 0..19 write their (elem, j-pair) firing rates ----
    int ge = gbase + wid * EPW + me;
    if (lid < 20 && ge < B) {
        float a0, a1; upk(a0, a1, accp);
        *reinterpret_cast<float2*>(out + (size_t)ge * 10 + 2 * jj) =
            make_float2(a0 * (1.0f / 28.0f), a1 * (1.0f / 28.0f));
    }
}

extern "C" void kernel_launch(void* const* d_in, const int* in_sizes, int n_in,
                              void* d_out, int out_size) {
    const float* x  = (const float*)d_in[0];
    const float* W1 = (const float*)d_in[1];
    const float* b1 = (const float*)d_in[2];
    const float* W2 = (const float*)d_in[3];
    const float* b2 = (const float*)d_in[4];
    float* out = (float*)d_out;

    int B = in_sizes[0] / 784;
    int smem = SMEMW * (int)sizeof(float);   // 57,920 B -> 3 blocks/SM (12 warps)

    cudaFuncSetAttribute(snn_kernel, cudaFuncAttributeMaxDynamicSharedMemorySize, smem);

    build_lut<<<40, 256>>>(W2);               // 10240 entries, one per thread

    int grid = (B + EPB - 1) / EPB;
    snn_kernel<<<grid, TPB, smem>>>(x, W1, b1, W2, b2, out, B);
}